// round 12
// baseline (speedup 1.0000x reference)
#include <cuda_runtime.h>
#include <cstdint>

#define BI 8
#define PI 8192
#define CI 91
#define NC 90
#define KTOP 1000
#define DET 100
#define CAP 131072
#define COLLECT 2048
#define NBUCK 2048
#define NMSB 30           // class-blocks per image
#define CPB 3             // classes per nms block (NMSB*CPB == NC)
#define CLIPV 4.135166556742356f
#define FULLM 0xFFFFFFFFu

// Persistent scratch (no allocations allowed in kernel_launch).
__device__ unsigned long long g_cand[BI][CAP];   // candidate keys per image
__device__ int g_cnt[BI];                        // zero-init; reset by select_kernel
__device__ unsigned long long g_keys[BI][COLLECT]; // collected then sorted keys
__device__ float4 g_box[BI][KTOP];               // decoded clipped boxes of top-1000
__device__ unsigned char g_sup[BI][KTOP];        // suppression flags (real entries only)

// BoxCoder.decode + clip_boxes_to_image, matching the reference op-for-op.
__device__ __forceinline__ void decode_box(
    float px1, float py1, float px2, float py2,
    float4 rg, float Wf, float Hf,
    float& x1, float& y1, float& x2, float& y2)
{
    float w  = px2 - px1;
    float h  = py2 - py1;
    float cx = px1 + 0.5f * w;
    float cy = py1 + 0.5f * h;
    float dx = rg.x / 10.0f;
    float dy = rg.y / 10.0f;
    float dw = fminf(rg.z / 5.0f, CLIPV);
    float dh = fminf(rg.w / 5.0f, CLIPV);
    float pcx = dx * w + cx;
    float pcy = dy * h + cy;
    float pw  = expf(dw) * w;
    float ph  = expf(dh) * h;
    x1 = fminf(fmaxf(pcx - 0.5f * pw, 0.0f), Wf);
    y1 = fminf(fmaxf(pcy - 0.5f * ph, 0.0f), Hf);
    x2 = fminf(fmaxf(pcx + 0.5f * pw, 0.0f), Wf);
    y2 = fminf(fmaxf(pcy + 0.5f * ph, 0.0f), Hf);
}

// One warp per proposal, 32 proposals per block (same image). MUFU-bound at
// its floor (91 exp per proposal is irreducible for exact softmax).
__global__ void __launch_bounds__(1024) phase1_kernel(
    const float* __restrict__ logits,
    const float* __restrict__ reg,
    const float* __restrict__ props,
    const int* __restrict__ hw)
{
    __shared__ unsigned long long stage[32 * NC];
    __shared__ int s_cnt, s_base;

    int tid  = threadIdx.x;
    int w    = tid >> 5;
    int lane = tid & 31;
    int gw = blockIdx.x * 32 + w;
    int b = gw >> 13;
    int p = gw & (PI - 1);
    float Hf = (float)hw[0];
    float Wf = (float)hw[1];

    if (tid == 0) s_cnt = 0;
    __syncthreads();

    const float* lg = logits + (size_t)gw * CI;
    float e0 = __expf(lg[lane]);
    float e1 = __expf(lg[lane + 32]);
    float e2 = (lane < CI - 64) ? __expf(lg[lane + 64]) : 0.0f;

    float s = e0 + e1 + e2;
    #pragma unroll
    for (int o = 16; o; o >>= 1) s += __shfl_xor_sync(FULLM, s, o);

    float4 pb = reinterpret_cast<const float4*>(props)[gw];
    const float4* rg4 = reinterpret_cast<const float4*>(reg) + (size_t)gw * CI;

    float pre = 0.0498f * s;
    #pragma unroll
    for (int j = 0; j < 3; j++) {
        int c   = lane + 32 * j;
        float e = (j == 0) ? e0 : (j == 1) ? e1 : e2;
        if (c >= 1 && c < CI && e > pre) {
            float score = e / s;                 // exact softmax value
            if (score > 0.05f) {
                float x1, y1, x2, y2;
                decode_box(pb.x, pb.y, pb.z, pb.w, rg4[c], Wf, Hf, x1, y1, x2, y2);
                if (x2 - x1 >= 0.01f && y2 - y1 >= 0.01f) {
                    unsigned idx = (unsigned)p * NC + (unsigned)(c - 1);
                    unsigned long long key =
                        ((unsigned long long)__float_as_uint(score) << 32)
                        | (unsigned long long)(0xFFFFFFFFu - idx);
                    int pos = atomicAdd(&s_cnt, 1);
                    stage[pos] = key;
                }
            }
        }
    }
    __syncthreads();

    if (tid == 0) s_base = atomicAdd(&g_cnt[b], s_cnt);
    __syncthreads();

    int n = s_cnt, base = s_base;
    for (int i = tid; i < n; i += 1024) {
        int off = base + i;
        if (off < CAP) g_cand[b][off] = stage[i];
    }
}

// One block per image: histogram -> parallel threshold -> warp-aggregated
// collect into g_keys (zero-padded to COLLECT). Resets g_cnt.
__global__ void __launch_bounds__(1024) select_kernel()
{
    __shared__ int hist[NBUCK];
    __shared__ int wsuf[32];
    __shared__ int s_T, s_cnt2, s_count;

    int b = blockIdx.x;
    int tid = threadIdx.x;
    int w = tid >> 5, lane = tid & 31;

    if (tid == 0) {
        s_count = min(g_cnt[b], CAP);
        g_cnt[b] = 0;
        s_T = 0;
        s_cnt2 = 0;
    }
    for (int i = tid; i < NBUCK; i += 1024) hist[i] = 0;
    __syncthreads();

    int count = s_count;
    for (int i = tid; i < count; i += 1024) {
        float sc = __uint_as_float((unsigned)(g_cand[b][i] >> 32));
        int bk = min(NBUCK - 1, (int)(sc * (float)NBUCK));
        atomicAdd(&hist[bk], 1);
    }
    __syncthreads();

    {
        int h0 = hist[2 * tid], h1 = hist[2 * tid + 1];
        int sown = h0 + h1;
        int v = sown;
        #pragma unroll
        for (int o = 1; o < 32; o <<= 1) {
            int t = __shfl_down_sync(FULLM, v, o);
            if (lane + o < 32) v += t;
        }
        if (lane == 0) wsuf[w] = v;
        __syncthreads();
        if (w == 0) {
            int vv = wsuf[lane];
            #pragma unroll
            for (int o = 1; o < 32; o <<= 1) {
                int t = __shfl_down_sync(FULLM, vv, o);
                if (lane + o < 32) vv += t;
            }
            wsuf[lane] = vv;
        }
        __syncthreads();
        int warp_excl = (w < 31) ? wsuf[w + 1] : 0;
        int after_me = warp_excl + (v - sown);
        int target = min(count, KTOP);
        int c1 = after_me + h1;
        int c0 = c1 + h0;
        int cand = -1;
        if      (c1 >= target) cand = 2 * tid + 1;
        else if (c0 >= target) cand = 2 * tid;
        #pragma unroll
        for (int o = 16; o; o >>= 1)
            cand = max(cand, __shfl_xor_sync(FULLM, cand, o));
        if (lane == 0 && cand >= 0) atomicMax(&s_T, cand);
    }
    __syncthreads();

    int T = s_T;
    int bound = (count + 1023) & ~1023;
    for (int i = tid; i < bound; i += 1024) {
        unsigned long long k = 0ULL;
        bool want = false;
        if (i < count) {
            k = g_cand[b][i];
            float sc = __uint_as_float((unsigned)(k >> 32));
            int bk = min(NBUCK - 1, (int)(sc * (float)NBUCK));
            want = (bk >= T);
        }
        unsigned m = __ballot_sync(FULLM, want);
        if (m) {
            int basew = 0;
            if (lane == 0) basew = atomicAdd(&s_cnt2, __popc(m));
            basew = __shfl_sync(FULLM, basew, 0);
            if (want) {
                int pos = basew + __popc(m & ((1u << lane) - 1u));
                if (pos < COLLECT) g_keys[b][pos] = k;
            }
        }
    }
    __syncthreads();

    int n2 = min(s_cnt2, COLLECT);
    for (int i = tid; i < COLLECT; i += 1024)
        if (i >= n2) g_keys[b][i] = 0ULL;
}

// One block per image: hybrid bitonic sort (descending, bit-identical network)
// then decode the top-1000 boxes into g_box.
__global__ void __launch_bounds__(1024) sortdec_kernel(
    const float* __restrict__ reg,
    const float* __restrict__ props,
    const int* __restrict__ hw)
{
    __shared__ unsigned long long keys[COLLECT];   // 16 KB
    int b = blockIdx.x;
    int tid = threadIdx.x;
    float Hf = (float)hw[0];
    float Wf = (float)hw[1];

    keys[tid] = g_keys[b][tid];
    keys[tid + 1024] = g_keys[b][tid + 1024];
    __syncthreads();

    {
        unsigned long long a, bb;
        a = keys[tid]; bb = keys[tid + 1024];
        #pragma unroll
        for (int k2 = 2; k2 <= 32; k2 <<= 1) {
            bool da = (tid & k2) == 0;
            #pragma unroll
            for (int j = k2 >> 1; j > 0; j >>= 1) {
                bool low = (tid & j) == 0;
                unsigned long long pa = __shfl_xor_sync(FULLM, a, j);
                unsigned long long pbv = __shfl_xor_sync(FULLM, bb, j);
                bool km = (low == da);
                a  = km ? (a  > pa  ? a  : pa ) : (a  < pa  ? a  : pa );
                bb = km ? (bb > pbv ? bb : pbv) : (bb < pbv ? bb : pbv);
            }
        }
        keys[tid] = a; keys[tid + 1024] = bb;
        __syncthreads();

        for (int k2 = 64; k2 <= COLLECT; k2 <<= 1) {
            for (int j = k2 >> 1; j >= 32; j >>= 1) {
                for (int i = tid; i < COLLECT; i += 1024) {
                    int l = i ^ j;
                    if (l > i) {
                        unsigned long long x = keys[i];
                        unsigned long long y = keys[l];
                        bool desc = (i & k2) == 0;
                        if (desc ? (x < y) : (x > y)) { keys[i] = y; keys[l] = x; }
                    }
                }
                __syncthreads();
            }
            a = keys[tid]; bb = keys[tid + 1024];
            bool da = (tid & k2) == 0;
            bool db = ((tid + 1024) & k2) == 0;
            #pragma unroll
            for (int j = 16; j > 0; j >>= 1) {
                bool low = (tid & j) == 0;
                unsigned long long pa = __shfl_xor_sync(FULLM, a, j);
                unsigned long long pbv = __shfl_xor_sync(FULLM, bb, j);
                bool kmA = (low == da);
                bool kmB = (low == db);
                a  = kmA ? (a  > pa  ? a  : pa ) : (a  < pa  ? a  : pa );
                bb = kmB ? (bb > pbv ? bb : pbv) : (bb < pbv ? bb : pbv);
            }
            keys[tid] = a; keys[tid + 1024] = bb;
            __syncthreads();
        }
    }

    // Persist sorted top-1000 keys + decode their boxes.
    if (tid < KTOP) {
        unsigned long long key = keys[tid];
        g_keys[b][tid] = key;
        unsigned sb = (unsigned)(key >> 32);
        float4 bx = make_float4(0.0f, 0.0f, 0.0f, 0.0f);
        if (sb != 0u) {
            unsigned idx = 0xFFFFFFFFu - (unsigned)(key & 0xFFFFFFFFu);
            int p = (int)(idx / NC);
            int c = (int)(idx % NC) + 1;
            size_t row = (size_t)b * PI + (size_t)p;
            float4 pb = reinterpret_cast<const float4*>(props)[row];
            float4 rg = reinterpret_cast<const float4*>(reg)[row * CI + c];
            float x1, y1, x2, y2;
            decode_box(pb.x, pb.y, pb.z, pb.w, rg, Wf, Hf, x1, y1, x2, y2);
            bx = make_float4(x1, y1, x2, y2);
        }
        g_box[b][tid] = bx;
    }
}

// Exact same fp expressions as the reference's _iou_matrix on offset boxes.
__device__ __forceinline__ bool iou_gt(
    float ax1, float ay1, float ax2, float ay2, float aa,
    float bx1, float by1, float bx2, float by2)
{
    float ba  = (bx2 - bx1) * (by2 - by1);
    float ltx = fmaxf(ax1, bx1);
    float lty = fmaxf(ay1, by1);
    float rbx = fminf(ax2, bx2);
    float rby = fminf(ay2, by2);
    float iw = fmaxf(rbx - ltx, 0.0f);
    float ih = fmaxf(rby - lty, 0.0f);
    float inter = iw * ih;
    float iou = inter / (aa + ba - inter + 1e-9f);
    return iou > 0.5f;
}

// Grid (BI, NMSB), 128 threads. Block (b, by) handles classes
// c = 1 + by*CPB + q, q in [0,CPB). R11 post-mortem: the gather did 32
// serially-dependent LDG->ballot iterations (L2 latency exposed each time,
// ~13us across the launch). Fix: ALL 128 threads first stage labels + boxes
// into SMEM (coalesced, MLP-pipelined), then the ballot sweep and the greedy
// loop run entirely on 29-cyc LDS. Work and output are bit-identical.
__global__ void __launch_bounds__(128) nms_kernel(const int* __restrict__ hw)
{
    __shared__ unsigned char slab[KTOP + 24];      // label per sorted entry
    __shared__ float4 sbox[KTOP];                  // 16 KB box stage
    __shared__ unsigned short clist[CPB][1024];
    __shared__ unsigned char csup[CPB][1024];

    int b = blockIdx.x;
    int by = blockIdx.y;
    int tid = threadIdx.x;
    int w = tid >> 5, lane = tid & 31;
    float Hf = (float)hw[0];
    float Wf = (float)hw[1];
    float offsc = fmaxf(Hf, Wf) + 1.0f;

    // Cooperative stage: 1000 keys -> labels, 1000 boxes -> smem.
    for (int i = tid; i < KTOP; i += 128) {
        unsigned long long k = g_keys[b][i];
        unsigned sb = (unsigned)(k >> 32);
        int lab = 0;                               // 0 = padding (no class)
        if (sb != 0u) {
            unsigned idx = 0xFFFFFFFFu - (unsigned)(k & 0xFFFFFFFFu);
            lab = (int)(idx % NC) + 1;
        }
        slab[i] = (unsigned char)lab;
        sbox[i] = g_box[b][i];
    }
    for (int i = KTOP + tid; i < KTOP + 24; i += 128) slab[i] = 0;
    __syncthreads();

    if (w < CPB) {
        int c = 1 + by * CPB + w;
        // Order-preserving gather of class-c entries (smem ballot sweep).
        int cnt = 0;
        for (int base = 0; base < KTOP; base += 32) {
            int i = base + lane;
            int lab = (int)slab[i];                // padded tail reads 0
            unsigned m = __ballot_sync(FULLM, lab == c);
            if (lab == c) {
                int pos = cnt + __popc(m & ((1u << lane) - 1u));
                clist[w][pos] = (unsigned short)i;
            }
            cnt += __popc(m);
        }
        for (int i = lane; i < cnt; i += 32) csup[w][i] = 0;
        __syncwarp();

        float off = (float)c * offsc;
        for (int il = 0; il < cnt; il++) {
            if (!csup[w][il]) {
                float4 A = sbox[clist[w][il]];
                float ax1 = A.x + off, ay1 = A.y + off;
                float ax2 = A.z + off, ay2 = A.w + off;
                float aa = (ax2 - ax1) * (ay2 - ay1);
                for (int jl = il + 1 + lane; jl < cnt; jl += 32) {
                    float4 Bx = sbox[clist[w][jl]];
                    float bx1 = Bx.x + off, by1 = Bx.y + off;
                    float bx2 = Bx.z + off, by2 = Bx.w + off;
                    if (iou_gt(ax1, ay1, ax2, ay2, aa, bx1, by1, bx2, by2))
                        csup[w][jl] = 1;
                }
            }
            __syncwarp();
        }

        for (int i = lane; i < cnt; i += 32)
            g_sup[b][clist[w][i]] = csup[w][i];
    }
}

// One block per image: compact kept entries in sorted order, emit top-100.
__global__ void __launch_bounds__(1024) emit_kernel(float* __restrict__ out)
{
    __shared__ int kept[DET];
    __shared__ int wcnt[32], wbase[32];
    __shared__ int s_n;

    int b = blockIdx.x;
    int tid = threadIdx.x;
    int w = tid >> 5, lane = tid & 31;

    unsigned long long key = (tid < KTOP) ? g_keys[b][tid] : 0ULL;
    unsigned sb = (unsigned)(key >> 32);
    bool keepf = (tid < KTOP) && (sb != 0u) && (g_sup[b][tid] == 0);

    unsigned m = __ballot_sync(FULLM, keepf);
    if (lane == 0) wcnt[w] = __popc(m);
    __syncthreads();
    if (w == 0) {
        int x = wcnt[lane];
        int e = x;
        #pragma unroll
        for (int o = 1; o < 32; o <<= 1) {
            int t = __shfl_up_sync(FULLM, e, o);
            if (lane >= o) e += t;
        }
        wbase[lane] = e - x;
        if (lane == 31) s_n = min(e, DET);
    }
    __syncthreads();
    if (keepf) {
        int pos = wbase[w] + __popc(m & ((1u << lane) - 1u));
        if (pos < DET) kept[pos] = tid;
    }
    __syncthreads();

    if (tid < DET) {
        float b0 = 0.0f, b1 = 0.0f, b2 = 0.0f, b3 = 0.0f, sc = 0.0f, lb = 0.0f;
        if (tid < s_n) {
            int i = kept[tid];
            unsigned long long k = g_keys[b][i];
            float4 Bx = g_box[b][i];
            b0 = Bx.x; b1 = Bx.y; b2 = Bx.z; b3 = Bx.w;
            sc = __uint_as_float((unsigned)(k >> 32));
            unsigned idx = 0xFFFFFFFFu - (unsigned)(k & 0xFFFFFFFFu);
            lb = (float)((int)(idx % NC) + 1);
        }
        float* ob = out + ((size_t)b * DET + tid) * 4;
        ob[0] = b0; ob[1] = b1; ob[2] = b2; ob[3] = b3;
        out[BI * DET * 4 + b * DET + tid] = sc;                 // scores
        out[BI * DET * 4 + BI * DET + b * DET + tid] = lb;      // labels (as float)
    }
}

extern "C" void kernel_launch(void* const* d_in, const int* in_sizes, int n_in,
                              void* d_out, int out_size)
{
    const float* logits = (const float*)d_in[0];   // [B,P,C]
    const float* reg    = (const float*)d_in[1];   // [B,P,4C]
    const float* props  = (const float*)d_in[2];   // [B,P,4]
    const int*   hw     = (const int*)d_in[3];     // [2]
    float* out = (float*)d_out;                    // boxes | scores | labels

    phase1_kernel<<<(BI * PI) / 32, 1024>>>(logits, reg, props, hw);
    select_kernel<<<BI, 1024>>>();
    sortdec_kernel<<<BI, 1024>>>(reg, props, hw);
    nms_kernel<<<dim3(BI, NMSB), 128>>>(hw);
    emit_kernel<<<BI, 1024>>>(out);
}

// round 13
// speedup vs baseline: 1.0267x; 1.0267x over previous
#include <cuda_runtime.h>
#include <cstdint>

#define BI 8
#define PI 8192
#define CI 91
#define NC 90
#define KTOP 1000
#define DET 100
#define CAP 131072
#define COLLECT 2048
#define NBUCK 2048
#define NMSB 3            // nms blocks per image
#define WPB 30            // warps per nms block (NMSB*WPB == NC)
#define CAPC 128
#define CLIPV 4.135166556742356f
#define FULLM 0xFFFFFFFFu

// Persistent scratch (no allocations allowed in kernel_launch).
__device__ unsigned long long g_cand[BI][CAP];   // candidate keys per image
__device__ int g_cnt[BI];                        // zero-init; reset by select_kernel
__device__ unsigned long long g_keys[BI][COLLECT]; // collected then sorted keys
__device__ float4 g_box[BI][KTOP];               // decoded clipped boxes of top-1000
__device__ unsigned char g_sup[BI][KTOP];        // suppression flags (real entries only)

// BoxCoder.decode + clip_boxes_to_image, matching the reference op-for-op.
__device__ __forceinline__ void decode_box(
    float px1, float py1, float px2, float py2,
    float4 rg, float Wf, float Hf,
    float& x1, float& y1, float& x2, float& y2)
{
    float w  = px2 - px1;
    float h  = py2 - py1;
    float cx = px1 + 0.5f * w;
    float cy = py1 + 0.5f * h;
    float dx = rg.x / 10.0f;
    float dy = rg.y / 10.0f;
    float dw = fminf(rg.z / 5.0f, CLIPV);
    float dh = fminf(rg.w / 5.0f, CLIPV);
    float pcx = dx * w + cx;
    float pcy = dy * h + cy;
    float pw  = expf(dw) * w;
    float ph  = expf(dh) * h;
    x1 = fminf(fmaxf(pcx - 0.5f * pw, 0.0f), Wf);
    y1 = fminf(fmaxf(pcy - 0.5f * ph, 0.0f), Hf);
    x2 = fminf(fmaxf(pcx + 0.5f * pw, 0.0f), Wf);
    y2 = fminf(fmaxf(pcy + 0.5f * ph, 0.0f), Hf);
}

// One warp per proposal, 32 proposals per block (same image). MUFU-bound at
// its floor (91 exp per proposal is irreducible for exact softmax).
__global__ void __launch_bounds__(1024) phase1_kernel(
    const float* __restrict__ logits,
    const float* __restrict__ reg,
    const float* __restrict__ props,
    const int* __restrict__ hw)
{
    __shared__ unsigned long long stage[32 * NC];
    __shared__ int s_cnt, s_base;

    int tid  = threadIdx.x;
    int w    = tid >> 5;
    int lane = tid & 31;
    int gw = blockIdx.x * 32 + w;
    int b = gw >> 13;
    int p = gw & (PI - 1);
    float Hf = (float)hw[0];
    float Wf = (float)hw[1];

    if (tid == 0) s_cnt = 0;
    __syncthreads();

    const float* lg = logits + (size_t)gw * CI;
    float e0 = __expf(lg[lane]);
    float e1 = __expf(lg[lane + 32]);
    float e2 = (lane < CI - 64) ? __expf(lg[lane + 64]) : 0.0f;

    float s = e0 + e1 + e2;
    #pragma unroll
    for (int o = 16; o; o >>= 1) s += __shfl_xor_sync(FULLM, s, o);

    float4 pb = reinterpret_cast<const float4*>(props)[gw];
    const float4* rg4 = reinterpret_cast<const float4*>(reg) + (size_t)gw * CI;

    float pre = 0.0498f * s;
    #pragma unroll
    for (int j = 0; j < 3; j++) {
        int c   = lane + 32 * j;
        float e = (j == 0) ? e0 : (j == 1) ? e1 : e2;
        if (c >= 1 && c < CI && e > pre) {
            float score = e / s;                 // exact softmax value
            if (score > 0.05f) {
                float x1, y1, x2, y2;
                decode_box(pb.x, pb.y, pb.z, pb.w, rg4[c], Wf, Hf, x1, y1, x2, y2);
                if (x2 - x1 >= 0.01f && y2 - y1 >= 0.01f) {
                    unsigned idx = (unsigned)p * NC + (unsigned)(c - 1);
                    unsigned long long key =
                        ((unsigned long long)__float_as_uint(score) << 32)
                        | (unsigned long long)(0xFFFFFFFFu - idx);
                    int pos = atomicAdd(&s_cnt, 1);
                    stage[pos] = key;
                }
            }
        }
    }
    __syncthreads();

    if (tid == 0) s_base = atomicAdd(&g_cnt[b], s_cnt);
    __syncthreads();

    int n = s_cnt, base = s_base;
    for (int i = tid; i < n; i += 1024) {
        int off = base + i;
        if (off < CAP) g_cand[b][off] = stage[i];
    }
}

// One block per image: histogram -> parallel threshold -> warp-aggregated
// collect into g_keys (zero-padded to COLLECT). Resets g_cnt.
__global__ void __launch_bounds__(1024) select_kernel()
{
    __shared__ int hist[NBUCK];
    __shared__ int wsuf[32];
    __shared__ int s_T, s_cnt2, s_count;

    int b = blockIdx.x;
    int tid = threadIdx.x;
    int w = tid >> 5, lane = tid & 31;

    if (tid == 0) {
        s_count = min(g_cnt[b], CAP);
        g_cnt[b] = 0;
        s_T = 0;
        s_cnt2 = 0;
    }
    for (int i = tid; i < NBUCK; i += 1024) hist[i] = 0;
    __syncthreads();

    int count = s_count;
    for (int i = tid; i < count; i += 1024) {
        float sc = __uint_as_float((unsigned)(g_cand[b][i] >> 32));
        int bk = min(NBUCK - 1, (int)(sc * (float)NBUCK));
        atomicAdd(&hist[bk], 1);
    }
    __syncthreads();

    {
        int h0 = hist[2 * tid], h1 = hist[2 * tid + 1];
        int sown = h0 + h1;
        int v = sown;
        #pragma unroll
        for (int o = 1; o < 32; o <<= 1) {
            int t = __shfl_down_sync(FULLM, v, o);
            if (lane + o < 32) v += t;
        }
        if (lane == 0) wsuf[w] = v;
        __syncthreads();
        if (w == 0) {
            int vv = wsuf[lane];
            #pragma unroll
            for (int o = 1; o < 32; o <<= 1) {
                int t = __shfl_down_sync(FULLM, vv, o);
                if (lane + o < 32) vv += t;
            }
            wsuf[lane] = vv;
        }
        __syncthreads();
        int warp_excl = (w < 31) ? wsuf[w + 1] : 0;
        int after_me = warp_excl + (v - sown);
        int target = min(count, KTOP);
        int c1 = after_me + h1;
        int c0 = c1 + h0;
        int cand = -1;
        if      (c1 >= target) cand = 2 * tid + 1;
        else if (c0 >= target) cand = 2 * tid;
        #pragma unroll
        for (int o = 16; o; o >>= 1)
            cand = max(cand, __shfl_xor_sync(FULLM, cand, o));
        if (lane == 0 && cand >= 0) atomicMax(&s_T, cand);
    }
    __syncthreads();

    int T = s_T;
    int bound = (count + 1023) & ~1023;
    for (int i = tid; i < bound; i += 1024) {
        unsigned long long k = 0ULL;
        bool want = false;
        if (i < count) {
            k = g_cand[b][i];
            float sc = __uint_as_float((unsigned)(k >> 32));
            int bk = min(NBUCK - 1, (int)(sc * (float)NBUCK));
            want = (bk >= T);
        }
        unsigned m = __ballot_sync(FULLM, want);
        if (m) {
            int basew = 0;
            if (lane == 0) basew = atomicAdd(&s_cnt2, __popc(m));
            basew = __shfl_sync(FULLM, basew, 0);
            if (want) {
                int pos = basew + __popc(m & ((1u << lane) - 1u));
                if (pos < COLLECT) g_keys[b][pos] = k;
            }
        }
    }
    __syncthreads();

    int n2 = min(s_cnt2, COLLECT);
    for (int i = tid; i < COLLECT; i += 1024)
        if (i >= n2) g_keys[b][i] = 0ULL;
}

// One block per image: hybrid bitonic sort (descending, bit-identical network)
// then decode the top-1000 boxes into g_box.
__global__ void __launch_bounds__(1024) sortdec_kernel(
    const float* __restrict__ reg,
    const float* __restrict__ props,
    const int* __restrict__ hw)
{
    __shared__ unsigned long long keys[COLLECT];   // 16 KB
    int b = blockIdx.x;
    int tid = threadIdx.x;
    float Hf = (float)hw[0];
    float Wf = (float)hw[1];

    keys[tid] = g_keys[b][tid];
    keys[tid + 1024] = g_keys[b][tid + 1024];
    __syncthreads();

    {
        unsigned long long a, bb;
        a = keys[tid]; bb = keys[tid + 1024];
        #pragma unroll
        for (int k2 = 2; k2 <= 32; k2 <<= 1) {
            bool da = (tid & k2) == 0;
            #pragma unroll
            for (int j = k2 >> 1; j > 0; j >>= 1) {
                bool low = (tid & j) == 0;
                unsigned long long pa = __shfl_xor_sync(FULLM, a, j);
                unsigned long long pbv = __shfl_xor_sync(FULLM, bb, j);
                bool km = (low == da);
                a  = km ? (a  > pa  ? a  : pa ) : (a  < pa  ? a  : pa );
                bb = km ? (bb > pbv ? bb : pbv) : (bb < pbv ? bb : pbv);
            }
        }
        keys[tid] = a; keys[tid + 1024] = bb;
        __syncthreads();

        for (int k2 = 64; k2 <= COLLECT; k2 <<= 1) {
            for (int j = k2 >> 1; j >= 32; j >>= 1) {
                for (int i = tid; i < COLLECT; i += 1024) {
                    int l = i ^ j;
                    if (l > i) {
                        unsigned long long x = keys[i];
                        unsigned long long y = keys[l];
                        bool desc = (i & k2) == 0;
                        if (desc ? (x < y) : (x > y)) { keys[i] = y; keys[l] = x; }
                    }
                }
                __syncthreads();
            }
            a = keys[tid]; bb = keys[tid + 1024];
            bool da = (tid & k2) == 0;
            bool db = ((tid + 1024) & k2) == 0;
            #pragma unroll
            for (int j = 16; j > 0; j >>= 1) {
                bool low = (tid & j) == 0;
                unsigned long long pa = __shfl_xor_sync(FULLM, a, j);
                unsigned long long pbv = __shfl_xor_sync(FULLM, bb, j);
                bool kmA = (low == da);
                bool kmB = (low == db);
                a  = kmA ? (a  > pa  ? a  : pa ) : (a  < pa  ? a  : pa );
                bb = kmB ? (bb > pbv ? bb : pbv) : (bb < pbv ? bb : pbv);
            }
            keys[tid] = a; keys[tid + 1024] = bb;
            __syncthreads();
        }
    }

    // Persist sorted top-1000 keys + decode their boxes.
    if (tid < KTOP) {
        unsigned long long key = keys[tid];
        g_keys[b][tid] = key;
        unsigned sb = (unsigned)(key >> 32);
        float4 bx = make_float4(0.0f, 0.0f, 0.0f, 0.0f);
        if (sb != 0u) {
            unsigned idx = 0xFFFFFFFFu - (unsigned)(key & 0xFFFFFFFFu);
            int p = (int)(idx / NC);
            int c = (int)(idx % NC) + 1;
            size_t row = (size_t)b * PI + (size_t)p;
            float4 pb = reinterpret_cast<const float4*>(props)[row];
            float4 rg = reinterpret_cast<const float4*>(reg)[row * CI + c];
            float x1, y1, x2, y2;
            decode_box(pb.x, pb.y, pb.z, pb.w, rg, Wf, Hf, x1, y1, x2, y2);
            bx = make_float4(x1, y1, x2, y2);
        }
        g_box[b][tid] = bx;
    }
}

// Exact same fp expressions as the reference's _iou_matrix on offset boxes.
__device__ __forceinline__ bool iou_gt(
    float ax1, float ay1, float ax2, float ay2, float aa,
    float bx1, float by1, float bx2, float by2)
{
    float ba  = (bx2 - bx1) * (by2 - by1);
    float ltx = fmaxf(ax1, bx1);
    float lty = fmaxf(ay1, by1);
    float rbx = fminf(ax2, bx2);
    float rby = fminf(ay2, by2);
    float iw = fmaxf(rbx - ltx, 0.0f);
    float ih = fmaxf(rby - lty, 0.0f);
    float inter = iw * ih;
    float iou = inter / (aa + ba - inter + 1e-9f);
    return iou > 0.5f;
}

// Grid (BI, NMSB=3), 960 threads = 30 warps, ONE class per warp.
// R12 post-mortem: 240 tiny 4-warp blocks each re-staged 24KB -> occ 7.7%,
// latency exposed. Now 24 blocks stage once with 960 threads and 30 warps
// hide each other's LDS/ballot latency. Classes are disjoint across warps,
// so a single per-block ssup[] is race-free; writeback covers exactly this
// block's classes. Comparison order and arithmetic unchanged.
__global__ void __launch_bounds__(960) nms_kernel(const int* __restrict__ hw)
{
    __shared__ unsigned char slab[KTOP + 24];      // label per sorted entry
    __shared__ float4 sbox[KTOP];                  // 16 KB box stage
    __shared__ unsigned char ssup[KTOP];           // suppression (this block's classes)
    __shared__ unsigned short clist[WPB][CAPC];    // per-warp class index list

    int b = blockIdx.x;
    int by = blockIdx.y;
    int tid = threadIdx.x;
    int w = tid >> 5, lane = tid & 31;
    float Hf = (float)hw[0];
    float Wf = (float)hw[1];
    float offsc = fmaxf(Hf, Wf) + 1.0f;
    int c = 1 + by * WPB + w;                      // this warp's class

    // Cooperative stage: 1000 keys -> labels, 1000 boxes, ssup=0.
    for (int i = tid; i < KTOP; i += 960) {
        unsigned long long k = g_keys[b][i];
        unsigned sb = (unsigned)(k >> 32);
        int lab = 0;                               // 0 = padding (no class)
        if (sb != 0u) {
            unsigned idx = 0xFFFFFFFFu - (unsigned)(k & 0xFFFFFFFFu);
            lab = (int)(idx % NC) + 1;
        }
        slab[i] = (unsigned char)lab;
        sbox[i] = g_box[b][i];
        ssup[i] = 0;
    }
    for (int i = KTOP + tid; i < KTOP + 24; i += 960) slab[i] = 0;
    __syncthreads();

    // Order-preserving gather of class-c entries (smem ballot sweep).
    int cnt = 0;
    for (int base = 0; base < KTOP; base += 32) {
        int i = base + lane;
        int lab = (int)slab[i];                    // padded tail reads 0
        unsigned m = __ballot_sync(FULLM, lab == c);
        if (lab == c) {
            int pos = cnt + __popc(m & ((1u << lane) - 1u));
            if (pos < CAPC) clist[w][pos] = (unsigned short)i;
        }
        cnt += __popc(m);
    }

    if (cnt <= CAPC) {
        // Fast path: greedy over the compact list.
        float off = (float)c * offsc;
        for (int il = 0; il < cnt; il++) {
            int ii = clist[w][il];
            if (!ssup[ii]) {
                float4 A = sbox[ii];
                float ax1 = A.x + off, ay1 = A.y + off;
                float ax2 = A.z + off, ay2 = A.w + off;
                float aa = (ax2 - ax1) * (ay2 - ay1);
                for (int jl = il + 1 + lane; jl < cnt; jl += 32) {
                    int jj = clist[w][jl];
                    float4 Bx = sbox[jj];
                    float bx1 = Bx.x + off, by1 = Bx.y + off;
                    float bx2 = Bx.z + off, by2 = Bx.w + off;
                    if (iou_gt(ax1, ay1, ax2, ay2, aa, bx1, by1, bx2, by2))
                        ssup[jj] = 1;
                }
            }
            __syncwarp();
        }
    } else {
        // Never-expected overflow: exact full-scan greedy for this class.
        float off = (float)c * offsc;
        for (int i = 0; i < KTOP; i++) {
            if ((int)slab[i] == c && !ssup[i]) {
                float4 A = sbox[i];
                float ax1 = A.x + off, ay1 = A.y + off;
                float ax2 = A.z + off, ay2 = A.w + off;
                float aa = (ax2 - ax1) * (ay2 - ay1);
                for (int j = i + 1 + lane; j < KTOP; j += 32) {
                    if ((int)slab[j] == c) {
                        float4 Bx = sbox[j];
                        float bx1 = Bx.x + off, by1 = Bx.y + off;
                        float bx2 = Bx.z + off, by2 = Bx.w + off;
                        if (iou_gt(ax1, ay1, ax2, ay2, aa, bx1, by1, bx2, by2))
                            ssup[j] = 1;
                    }
                }
            }
            __syncwarp();
        }
    }
    __syncthreads();

    // Writeback: entries whose class belongs to this block.
    int clo = 1 + by * WPB, chi = clo + WPB - 1;
    for (int i = tid; i < KTOP; i += 960) {
        int lab = (int)slab[i];
        if (lab >= clo && lab <= chi) g_sup[b][i] = ssup[i];
    }
}

// One block per image: compact kept entries in sorted order, emit top-100.
__global__ void __launch_bounds__(1024) emit_kernel(float* __restrict__ out)
{
    __shared__ int kept[DET];
    __shared__ int wcnt[32], wbase[32];
    __shared__ int s_n;

    int b = blockIdx.x;
    int tid = threadIdx.x;
    int w = tid >> 5, lane = tid & 31;

    unsigned long long key = (tid < KTOP) ? g_keys[b][tid] : 0ULL;
    unsigned sb = (unsigned)(key >> 32);
    bool keepf = (tid < KTOP) && (sb != 0u) && (g_sup[b][tid] == 0);

    unsigned m = __ballot_sync(FULLM, keepf);
    if (lane == 0) wcnt[w] = __popc(m);
    __syncthreads();
    if (w == 0) {
        int x = wcnt[lane];
        int e = x;
        #pragma unroll
        for (int o = 1; o < 32; o <<= 1) {
            int t = __shfl_up_sync(FULLM, e, o);
            if (lane >= o) e += t;
        }
        wbase[lane] = e - x;
        if (lane == 31) s_n = min(e, DET);
    }
    __syncthreads();
    if (keepf) {
        int pos = wbase[w] + __popc(m & ((1u << lane) - 1u));
        if (pos < DET) kept[pos] = tid;
    }
    __syncthreads();

    if (tid < DET) {
        float b0 = 0.0f, b1 = 0.0f, b2 = 0.0f, b3 = 0.0f, sc = 0.0f, lb = 0.0f;
        if (tid < s_n) {
            int i = kept[tid];
            unsigned long long k = g_keys[b][i];
            float4 Bx = g_box[b][i];
            b0 = Bx.x; b1 = Bx.y; b2 = Bx.z; b3 = Bx.w;
            sc = __uint_as_float((unsigned)(k >> 32));
            unsigned idx = 0xFFFFFFFFu - (unsigned)(k & 0xFFFFFFFFu);
            lb = (float)((int)(idx % NC) + 1);
        }
        float* ob = out + ((size_t)b * DET + tid) * 4;
        ob[0] = b0; ob[1] = b1; ob[2] = b2; ob[3] = b3;
        out[BI * DET * 4 + b * DET + tid] = sc;                 // scores
        out[BI * DET * 4 + BI * DET + b * DET + tid] = lb;      // labels (as float)
    }
}

extern "C" void kernel_launch(void* const* d_in, const int* in_sizes, int n_in,
                              void* d_out, int out_size)
{
    const float* logits = (const float*)d_in[0];   // [B,P,C]
    const float* reg    = (const float*)d_in[1];   // [B,P,4C]
    const float* props  = (const float*)d_in[2];   // [B,P,4]
    const int*   hw     = (const int*)d_in[3];     // [2]
    float* out = (float*)d_out;                    // boxes | scores | labels

    phase1_kernel<<<(BI * PI) / 32, 1024>>>(logits, reg, props, hw);
    select_kernel<<<BI, 1024>>>();
    sortdec_kernel<<<BI, 1024>>>(reg, props, hw);
    nms_kernel<<<dim3(BI, NMSB), 960>>>(hw);
    emit_kernel<<<BI, 1024>>>(out);
}

// round 14
// speedup vs baseline: 1.0444x; 1.0172x over previous
#include <cuda_runtime.h>
#include <cstdint>

#define BI 8
#define PI 8192
#define CI 91
#define NC 90
#define KTOP 1000
#define DET 100
#define CAP 131072
#define COLLECT 2048
#define NBUCK 2048
#define NMSB 3            // nms blocks per image
#define WPB 30            // warps per nms block (NMSB*WPB == NC)
#define CAPC 128
#define CLIPV 4.135166556742356f
#define FULLM 0xFFFFFFFFu

// Persistent scratch (no allocations allowed in kernel_launch).
__device__ unsigned long long g_cand[BI][CAP];   // candidate keys per image
__device__ int g_cnt[BI];                        // zero-init; reset by selsort_kernel
__device__ unsigned long long g_keys[BI][KTOP];  // sorted top-1000 keys
__device__ float4 g_box[BI][KTOP];               // decoded clipped boxes of top-1000
__device__ unsigned char g_sup[BI][KTOP];        // suppression flags

// BoxCoder.decode + clip_boxes_to_image, matching the reference op-for-op.
__device__ __forceinline__ void decode_box(
    float px1, float py1, float px2, float py2,
    float4 rg, float Wf, float Hf,
    float& x1, float& y1, float& x2, float& y2)
{
    float w  = px2 - px1;
    float h  = py2 - py1;
    float cx = px1 + 0.5f * w;
    float cy = py1 + 0.5f * h;
    float dx = rg.x / 10.0f;
    float dy = rg.y / 10.0f;
    float dw = fminf(rg.z / 5.0f, CLIPV);
    float dh = fminf(rg.w / 5.0f, CLIPV);
    float pcx = dx * w + cx;
    float pcy = dy * h + cy;
    float pw  = expf(dw) * w;
    float ph  = expf(dh) * h;
    x1 = fminf(fmaxf(pcx - 0.5f * pw, 0.0f), Wf);
    y1 = fminf(fmaxf(pcy - 0.5f * ph, 0.0f), Hf);
    x2 = fminf(fmaxf(pcx + 0.5f * pw, 0.0f), Wf);
    y2 = fminf(fmaxf(pcy + 0.5f * ph, 0.0f), Hf);
}

// 256 threads = 8 warps; each warp handles FOUR proposals (32/block, same
// image). R13 model fix: phase1 was never MUFU-bound (196k exp warp-instrs
// ~ 1.7us chip-wide) — it was a per-warp latency chain (3 dependent LDGs ->
// exp -> 5xSHFL). 4 proposals/warp gives 4x MLP on the loads and 4x ILP on
// the shuffle chains. Same arithmetic per proposal.
__global__ void __launch_bounds__(256) phase1_kernel(
    const float* __restrict__ logits,
    const float* __restrict__ reg,
    const float* __restrict__ props,
    const int* __restrict__ hw)
{
    __shared__ unsigned long long stage[32 * NC];   // 2880 = hard upper bound
    __shared__ int s_cnt, s_base;

    int tid  = threadIdx.x;
    int w    = tid >> 5;
    int lane = tid & 31;
    int pbase = blockIdx.x * 32 + w * 4;   // first of this warp's 4 proposals
    int b = (blockIdx.x * 32) >> 13;       // image id (block spans one image)
    float Hf = (float)hw[0];
    float Wf = (float)hw[1];

    if (tid == 0) s_cnt = 0;
    __syncthreads();

    // Issue ALL loads up front (12 row-loads + 4 prop float4s in flight).
    float l0[4], l1[4], l2[4];
    float4 pb[4];
    #pragma unroll
    for (int q = 0; q < 4; q++) {
        const float* lg = logits + (size_t)(pbase + q) * CI;
        l0[q] = lg[lane];
        l1[q] = lg[lane + 32];
        l2[q] = (lane < CI - 64) ? lg[lane + 64] : 0.0f;
        pb[q] = reinterpret_cast<const float4*>(props)[pbase + q];
    }

    float e0[4], e1[4], e2[4], s[4];
    #pragma unroll
    for (int q = 0; q < 4; q++) {
        e0[q] = __expf(l0[q]);
        e1[q] = __expf(l1[q]);
        e2[q] = (lane < CI - 64) ? __expf(l2[q]) : 0.0f;
        s[q] = e0[q] + e1[q] + e2[q];
    }
    // 4 independent reduction chains, interleaved (ILP hides SHFL latency).
    #pragma unroll
    for (int o = 16; o; o >>= 1) {
        #pragma unroll
        for (int q = 0; q < 4; q++)
            s[q] += __shfl_xor_sync(FULLM, s[q], o);
    }

    #pragma unroll
    for (int q = 0; q < 4; q++) {
        int p = (pbase + q) & (PI - 1);
        const float4* rg4 = reinterpret_cast<const float4*>(reg)
                          + (size_t)(pbase + q) * CI;
        float pre = 0.0498f * s[q];
        #pragma unroll
        for (int j = 0; j < 3; j++) {
            int c   = lane + 32 * j;
            float e = (j == 0) ? e0[q] : (j == 1) ? e1[q] : e2[q];
            if (c >= 1 && c < CI && e > pre) {
                float score = e / s[q];          // exact softmax value
                if (score > 0.05f) {
                    float x1, y1, x2, y2;
                    decode_box(pb[q].x, pb[q].y, pb[q].z, pb[q].w,
                               rg4[c], Wf, Hf, x1, y1, x2, y2);
                    if (x2 - x1 >= 0.01f && y2 - y1 >= 0.01f) {
                        unsigned idx = (unsigned)p * NC + (unsigned)(c - 1);
                        unsigned long long key =
                            ((unsigned long long)__float_as_uint(score) << 32)
                            | (unsigned long long)(0xFFFFFFFFu - idx);
                        int pos = atomicAdd(&s_cnt, 1);
                        stage[pos] = key;
                    }
                }
            }
        }
    }
    __syncthreads();

    if (tid == 0) s_base = atomicAdd(&g_cnt[b], s_cnt);
    __syncthreads();

    int n = s_cnt, base = s_base;
    for (int i = tid; i < n; i += 256) {
        int off = base + i;
        if (off < CAP) g_cand[b][off] = stage[i];
    }
}

// FUSED select+sort+decode: one block per image. Histogram -> parallel
// threshold -> warp-aggregated collect into SMEM -> hybrid bitonic sort ->
// write sorted top-1000 keys + decoded boxes. Resets g_cnt.
__global__ void __launch_bounds__(1024) selsort_kernel(
    const float* __restrict__ reg,
    const float* __restrict__ props,
    const int* __restrict__ hw)
{
    __shared__ unsigned long long keys[COLLECT];   // 16 KB
    __shared__ int hist[NBUCK];                    // 8 KB
    __shared__ int wsuf[32];
    __shared__ int s_T, s_cnt2, s_count;

    int b = blockIdx.x;
    int tid = threadIdx.x;
    int w = tid >> 5, lane = tid & 31;
    float Hf = (float)hw[0];
    float Wf = (float)hw[1];

    if (tid == 0) {
        s_count = min(g_cnt[b], CAP);
        g_cnt[b] = 0;
        s_T = 0;
        s_cnt2 = 0;
    }
    for (int i = tid; i < NBUCK; i += 1024) hist[i] = 0;
    __syncthreads();

    int count = s_count;
    for (int i = tid; i < count; i += 1024) {
        float sc = __uint_as_float((unsigned)(g_cand[b][i] >> 32));
        int bk = min(NBUCK - 1, (int)(sc * (float)NBUCK));
        atomicAdd(&hist[bk], 1);
    }
    __syncthreads();

    {
        int h0 = hist[2 * tid], h1 = hist[2 * tid + 1];
        int sown = h0 + h1;
        int v = sown;
        #pragma unroll
        for (int o = 1; o < 32; o <<= 1) {
            int t = __shfl_down_sync(FULLM, v, o);
            if (lane + o < 32) v += t;
        }
        if (lane == 0) wsuf[w] = v;
        __syncthreads();
        if (w == 0) {
            int vv = wsuf[lane];
            #pragma unroll
            for (int o = 1; o < 32; o <<= 1) {
                int t = __shfl_down_sync(FULLM, vv, o);
                if (lane + o < 32) vv += t;
            }
            wsuf[lane] = vv;
        }
        __syncthreads();
        int warp_excl = (w < 31) ? wsuf[w + 1] : 0;
        int after_me = warp_excl + (v - sown);
        int target = min(count, KTOP);
        int c1 = after_me + h1;
        int c0 = c1 + h0;
        int cand = -1;
        if      (c1 >= target) cand = 2 * tid + 1;
        else if (c0 >= target) cand = 2 * tid;
        #pragma unroll
        for (int o = 16; o; o >>= 1)
            cand = max(cand, __shfl_xor_sync(FULLM, cand, o));
        if (lane == 0 && cand >= 0) atomicMax(&s_T, cand);
    }
    __syncthreads();

    // Warp-aggregated collect straight into the smem sort buffer.
    int T = s_T;
    int bound = (count + 1023) & ~1023;
    for (int i = tid; i < bound; i += 1024) {
        unsigned long long k = 0ULL;
        bool want = false;
        if (i < count) {
            k = g_cand[b][i];
            float sc = __uint_as_float((unsigned)(k >> 32));
            int bk = min(NBUCK - 1, (int)(sc * (float)NBUCK));
            want = (bk >= T);
        }
        unsigned m = __ballot_sync(FULLM, want);
        if (m) {
            int basew = 0;
            if (lane == 0) basew = atomicAdd(&s_cnt2, __popc(m));
            basew = __shfl_sync(FULLM, basew, 0);
            if (want) {
                int pos = basew + __popc(m & ((1u << lane) - 1u));
                if (pos < COLLECT) keys[pos] = k;
            }
        }
    }
    __syncthreads();

    int n2 = min(s_cnt2, COLLECT);
    for (int i = tid; i < COLLECT; i += 1024)
        if (i >= n2) keys[i] = 0ULL;
    __syncthreads();

    // Hybrid bitonic sort, descending (bit-identical comparison network).
    {
        unsigned long long a, bb;
        a = keys[tid]; bb = keys[tid + 1024];
        #pragma unroll
        for (int k2 = 2; k2 <= 32; k2 <<= 1) {
            bool da = (tid & k2) == 0;
            #pragma unroll
            for (int j = k2 >> 1; j > 0; j >>= 1) {
                bool low = (tid & j) == 0;
                unsigned long long pa = __shfl_xor_sync(FULLM, a, j);
                unsigned long long pbv = __shfl_xor_sync(FULLM, bb, j);
                bool km = (low == da);
                a  = km ? (a  > pa  ? a  : pa ) : (a  < pa  ? a  : pa );
                bb = km ? (bb > pbv ? bb : pbv) : (bb < pbv ? bb : pbv);
            }
        }
        keys[tid] = a; keys[tid + 1024] = bb;
        __syncthreads();

        for (int k2 = 64; k2 <= COLLECT; k2 <<= 1) {
            for (int j = k2 >> 1; j >= 32; j >>= 1) {
                for (int i = tid; i < COLLECT; i += 1024) {
                    int l = i ^ j;
                    if (l > i) {
                        unsigned long long x = keys[i];
                        unsigned long long y = keys[l];
                        bool desc = (i & k2) == 0;
                        if (desc ? (x < y) : (x > y)) { keys[i] = y; keys[l] = x; }
                    }
                }
                __syncthreads();
            }
            a = keys[tid]; bb = keys[tid + 1024];
            bool da = (tid & k2) == 0;
            bool db = ((tid + 1024) & k2) == 0;
            #pragma unroll
            for (int j = 16; j > 0; j >>= 1) {
                bool low = (tid & j) == 0;
                unsigned long long pa = __shfl_xor_sync(FULLM, a, j);
                unsigned long long pbv = __shfl_xor_sync(FULLM, bb, j);
                bool kmA = (low == da);
                bool kmB = (low == db);
                a  = kmA ? (a  > pa  ? a  : pa ) : (a  < pa  ? a  : pa );
                bb = kmB ? (bb > pbv ? bb : pbv) : (bb < pbv ? bb : pbv);
            }
            keys[tid] = a; keys[tid + 1024] = bb;
            __syncthreads();
        }
    }

    // Persist sorted top-1000 keys + decode their boxes.
    if (tid < KTOP) {
        unsigned long long key = keys[tid];
        g_keys[b][tid] = key;
        unsigned sb = (unsigned)(key >> 32);
        float4 bx = make_float4(0.0f, 0.0f, 0.0f, 0.0f);
        if (sb != 0u) {
            unsigned idx = 0xFFFFFFFFu - (unsigned)(key & 0xFFFFFFFFu);
            int p = (int)(idx / NC);
            int c = (int)(idx % NC) + 1;
            size_t row = (size_t)b * PI + (size_t)p;
            float4 pbv = reinterpret_cast<const float4*>(props)[row];
            float4 rg = reinterpret_cast<const float4*>(reg)[row * CI + c];
            float x1, y1, x2, y2;
            decode_box(pbv.x, pbv.y, pbv.z, pbv.w, rg, Wf, Hf, x1, y1, x2, y2);
            bx = make_float4(x1, y1, x2, y2);
        }
        g_box[b][tid] = bx;
    }
}

// Exact same fp expressions as the reference's _iou_matrix on offset boxes.
__device__ __forceinline__ bool iou_gt(
    float ax1, float ay1, float ax2, float ay2, float aa,
    float bx1, float by1, float bx2, float by2)
{
    float ba  = (bx2 - bx1) * (by2 - by1);
    float ltx = fmaxf(ax1, bx1);
    float lty = fmaxf(ay1, by1);
    float rbx = fminf(ax2, bx2);
    float rby = fminf(ay2, by2);
    float iw = fmaxf(rbx - ltx, 0.0f);
    float ih = fmaxf(rby - lty, 0.0f);
    float inter = iw * ih;
    float iou = inter / (aa + ba - inter + 1e-9f);
    return iou > 0.5f;
}

// Grid (BI, NMSB=3), 960 threads = 30 warps, ONE class per warp.
// Classes are disjoint across warps -> per-block ssup[] is race-free;
// writeback covers exactly this block's classes.
__global__ void __launch_bounds__(960) nms_kernel(const int* __restrict__ hw)
{
    __shared__ unsigned char slab[KTOP + 24];      // label per sorted entry
    __shared__ float4 sbox[KTOP];                  // 16 KB box stage
    __shared__ unsigned char ssup[KTOP];           // suppression (this block's classes)
    __shared__ unsigned short clist[WPB][CAPC];    // per-warp class index list

    int b = blockIdx.x;
    int by = blockIdx.y;
    int tid = threadIdx.x;
    int w = tid >> 5, lane = tid & 31;
    float Hf = (float)hw[0];
    float Wf = (float)hw[1];
    float offsc = fmaxf(Hf, Wf) + 1.0f;
    int c = 1 + by * WPB + w;                      // this warp's class

    // Cooperative stage: 1000 keys -> labels, 1000 boxes, ssup=0.
    for (int i = tid; i < KTOP; i += 960) {
        unsigned long long k = g_keys[b][i];
        unsigned sb = (unsigned)(k >> 32);
        int lab = 0;                               // 0 = padding (no class)
        if (sb != 0u) {
            unsigned idx = 0xFFFFFFFFu - (unsigned)(k & 0xFFFFFFFFu);
            lab = (int)(idx % NC) + 1;
        }
        slab[i] = (unsigned char)lab;
        sbox[i] = g_box[b][i];
        ssup[i] = 0;
    }
    for (int i = KTOP + tid; i < KTOP + 24; i += 960) slab[i] = 0;
    __syncthreads();

    // Order-preserving gather of class-c entries (smem ballot sweep).
    int cnt = 0;
    for (int base = 0; base < KTOP; base += 32) {
        int i = base + lane;
        int lab = (int)slab[i];                    // padded tail reads 0
        unsigned m = __ballot_sync(FULLM, lab == c);
        if (lab == c) {
            int pos = cnt + __popc(m & ((1u << lane) - 1u));
            if (pos < CAPC) clist[w][pos] = (unsigned short)i;
        }
        cnt += __popc(m);
    }

    if (cnt <= CAPC) {
        float off = (float)c * offsc;
        for (int il = 0; il < cnt; il++) {
            int ii = clist[w][il];
            if (!ssup[ii]) {
                float4 A = sbox[ii];
                float ax1 = A.x + off, ay1 = A.y + off;
                float ax2 = A.z + off, ay2 = A.w + off;
                float aa = (ax2 - ax1) * (ay2 - ay1);
                for (int jl = il + 1 + lane; jl < cnt; jl += 32) {
                    int jj = clist[w][jl];
                    float4 Bx = sbox[jj];
                    float bx1 = Bx.x + off, by1 = Bx.y + off;
                    float bx2 = Bx.z + off, by2 = Bx.w + off;
                    if (iou_gt(ax1, ay1, ax2, ay2, aa, bx1, by1, bx2, by2))
                        ssup[jj] = 1;
                }
            }
            __syncwarp();
        }
    } else {
        // Never-expected overflow: exact full-scan greedy for this class.
        float off = (float)c * offsc;
        for (int i = 0; i < KTOP; i++) {
            if ((int)slab[i] == c && !ssup[i]) {
                float4 A = sbox[i];
                float ax1 = A.x + off, ay1 = A.y + off;
                float ax2 = A.z + off, ay2 = A.w + off;
                float aa = (ax2 - ax1) * (ay2 - ay1);
                for (int j = i + 1 + lane; j < KTOP; j += 32) {
                    if ((int)slab[j] == c) {
                        float4 Bx = sbox[j];
                        float bx1 = Bx.x + off, by1 = Bx.y + off;
                        float bx2 = Bx.z + off, by2 = Bx.w + off;
                        if (iou_gt(ax1, ay1, ax2, ay2, aa, bx1, by1, bx2, by2))
                            ssup[j] = 1;
                    }
                }
            }
            __syncwarp();
        }
    }
    __syncthreads();

    // Writeback: entries whose class belongs to this block.
    int clo = 1 + by * WPB, chi = clo + WPB - 1;
    for (int i = tid; i < KTOP; i += 960) {
        int lab = (int)slab[i];
        if (lab >= clo && lab <= chi) g_sup[b][i] = ssup[i];
    }
}

// One block per image: compact kept entries in sorted order, emit top-100.
__global__ void __launch_bounds__(1024) emit_kernel(float* __restrict__ out)
{
    __shared__ int kept[DET];
    __shared__ int wcnt[32], wbase[32];
    __shared__ int s_n;

    int b = blockIdx.x;
    int tid = threadIdx.x;
    int w = tid >> 5, lane = tid & 31;

    unsigned long long key = (tid < KTOP) ? g_keys[b][tid] : 0ULL;
    unsigned sb = (unsigned)(key >> 32);
    bool keepf = (tid < KTOP) && (sb != 0u) && (g_sup[b][tid] == 0);

    unsigned m = __ballot_sync(FULLM, keepf);
    if (lane == 0) wcnt[w] = __popc(m);
    __syncthreads();
    if (w == 0) {
        int x = wcnt[lane];
        int e = x;
        #pragma unroll
        for (int o = 1; o < 32; o <<= 1) {
            int t = __shfl_up_sync(FULLM, e, o);
            if (lane >= o) e += t;
        }
        wbase[lane] = e - x;
        if (lane == 31) s_n = min(e, DET);
    }
    __syncthreads();
    if (keepf) {
        int pos = wbase[w] + __popc(m & ((1u << lane) - 1u));
        if (pos < DET) kept[pos] = tid;
    }
    __syncthreads();

    if (tid < DET) {
        float b0 = 0.0f, b1 = 0.0f, b2 = 0.0f, b3 = 0.0f, sc = 0.0f, lb = 0.0f;
        if (tid < s_n) {
            int i = kept[tid];
            unsigned long long k = g_keys[b][i];
            float4 Bx = g_box[b][i];
            b0 = Bx.x; b1 = Bx.y; b2 = Bx.z; b3 = Bx.w;
            sc = __uint_as_float((unsigned)(k >> 32));
            unsigned idx = 0xFFFFFFFFu - (unsigned)(k & 0xFFFFFFFFu);
            lb = (float)((int)(idx % NC) + 1);
        }
        float* ob = out + ((size_t)b * DET + tid) * 4;
        ob[0] = b0; ob[1] = b1; ob[2] = b2; ob[3] = b3;
        out[BI * DET * 4 + b * DET + tid] = sc;                 // scores
        out[BI * DET * 4 + BI * DET + b * DET + tid] = lb;      // labels (as float)
    }
}

extern "C" void kernel_launch(void* const* d_in, const int* in_sizes, int n_in,
                              void* d_out, int out_size)
{
    const float* logits = (const float*)d_in[0];   // [B,P,C]
    const float* reg    = (const float*)d_in[1];   // [B,P,4C]
    const float* props  = (const float*)d_in[2];   // [B,P,4]
    const int*   hw     = (const int*)d_in[3];     // [2]
    float* out = (float*)d_out;                    // boxes | scores | labels

    phase1_kernel<<<(BI * PI) / 32, 256>>>(logits, reg, props, hw);
    selsort_kernel<<<BI, 1024>>>(reg, props, hw);
    nms_kernel<<<dim3(BI, NMSB), 960>>>(hw);
    emit_kernel<<<BI, 1024>>>(out);
}